// round 2
// baseline (speedup 1.0000x reference)
#include <cuda_runtime.h>
#include <cstdint>

#define E_  8
#define H_  8
#define D_  512
#define B_  16
#define S_  256
#define DK_ 64

// ---------------- scratch (device globals: allowed; no runtime alloc) ----------------
__device__ float g_xsum_part[B_ * 8 * D_];          // 16*8*512
__device__ int   g_sel[B_];
__device__ float g_qh[B_ * H_ * S_ * DK_];          // 8 MB
__device__ float g_kh[B_ * H_ * S_ * DK_];          // 8 MB
__device__ float g_vh[B_ * H_ * S_ * DK_];          // 8 MB
__device__ float g_sc[B_ * H_ * S_ * S_];           // 33.5 MB
__device__ float g_ctx[B_ * S_ * D_];               // 8 MB

// ---------------- threefry2x32 (exact JAX replication, key=(0,42)) ----------------
__device__ __forceinline__ uint32_t rotl32(uint32_t x, int r) {
    return (x << r) | (x >> (32 - r));
}

__device__ void threefry2x32(uint32_t k0, uint32_t k1, uint32_t c0, uint32_t c1,
                             uint32_t* o0, uint32_t* o1) {
    uint32_t ks2 = k0 ^ k1 ^ 0x1BD11BDAu;
    uint32_t x0 = c0 + k0;
    uint32_t x1 = c1 + k1;
    const int R0[4] = {13, 15, 26, 6};
    const int R1[4] = {17, 29, 16, 24};
#pragma unroll
    for (int i = 0; i < 4; i++) { x0 += x1; x1 = rotl32(x1, R0[i]); x1 ^= x0; }
    x0 += k1;  x1 += ks2 + 1u;
#pragma unroll
    for (int i = 0; i < 4; i++) { x0 += x1; x1 = rotl32(x1, R1[i]); x1 ^= x0; }
    x0 += ks2; x1 += k0 + 2u;
#pragma unroll
    for (int i = 0; i < 4; i++) { x0 += x1; x1 = rotl32(x1, R0[i]); x1 ^= x0; }
    x0 += k0;  x1 += k1 + 3u;
#pragma unroll
    for (int i = 0; i < 4; i++) { x0 += x1; x1 = rotl32(x1, R1[i]); x1 ^= x0; }
    x0 += k1;  x1 += ks2 + 4u;
#pragma unroll
    for (int i = 0; i < 4; i++) { x0 += x1; x1 = rotl32(x1, R0[i]); x1 ^= x0; }
    x0 += ks2; x1 += k0 + 5u;
    *o0 = x0; *o1 = x1;
}

// XLA ErfInv32 polynomial
__device__ float erfinv_xla(float x) {
    float w = -log1pf(-x * x);
    float p;
    if (w < 5.0f) {
        w -= 2.5f;
        p = 2.81022636e-08f;
        p = fmaf(p, w, 3.43273939e-07f);
        p = fmaf(p, w, -3.5233877e-06f);
        p = fmaf(p, w, -4.39150654e-06f);
        p = fmaf(p, w, 0.00021858087f);
        p = fmaf(p, w, -0.00125372503f);
        p = fmaf(p, w, -0.00417768164f);
        p = fmaf(p, w, 0.246640727f);
        p = fmaf(p, w, 1.50140941f);
    } else {
        w = sqrtf(w) - 3.0f;
        p = -0.000200214257f;
        p = fmaf(p, w, 0.000100950558f);
        p = fmaf(p, w, 0.00134934322f);
        p = fmaf(p, w, -0.00367342844f);
        p = fmaf(p, w, 0.00573950773f);
        p = fmaf(p, w, -0.0076224613f);
        p = fmaf(p, w, 0.00943887047f);
        p = fmaf(p, w, 1.00167406f);
        p = fmaf(p, w, 2.83297682f);
    }
    return p * x;
}

// ---------------- K1: partial sums of q over S ----------------
__global__ void xsum_kernel(const float* __restrict__ q) {
    int b = blockIdx.x, part = blockIdx.y, d = threadIdx.x;   // block 512
    const float* p = q + ((size_t)b * S_ + part * 32) * D_ + d;
    float acc = 0.0f;
#pragma unroll
    for (int s = 0; s < 32; s++) acc += p[s * D_];
    g_xsum_part[(b * 8 + part) * D_ + d] = acc;
}

// ---------------- K2: gating (1 block, 128 threads) ----------------
__global__ void gating_kernel(const float* __restrict__ wg,
                              const float* __restrict__ wn,
                              float* __restrict__ d_out, int out_size) {
    int tid = threadIdx.x;          // 0..127  => (b, e)
    int b = tid >> 3, e = tid & 7;

    float cl = 0.0f, rn = 0.0f;
    for (int i = 0; i < D_; i++) {
        float xs = 0.0f;
#pragma unroll
        for (int p = 0; p < 8; p++) xs += g_xsum_part[(b * 8 + p) * D_ + i];
        cl = fmaf(xs, wg[i * E_ + e], cl);
        rn = fmaf(xs, wn[i * E_ + e], rn);
    }

    // softplus = logaddexp(x, 0) = max(x,0) + log1p(exp(-|x|))
    float sp = fmaxf(rn, 0.0f) + log1pf(expf(-fabsf(rn)));
    float stdv = sp + 0.01f;

    // Partitionable threefry normal (JAX >= 0.4.36 default):
    // element j uses 64-bit counter j -> (hi=0, lo=j); 32-bit draw = o0 ^ o1.
    float z;
    {
        uint32_t j = (uint32_t)tid;
        uint32_t o0, o1;
        threefry2x32(0u, 42u, 0u, j, &o0, &o1);
        uint32_t bits = o0 ^ o1;
        uint32_t fb = (bits >> 9) | 0x3f800000u;
        float f = __uint_as_float(fb) - 1.0f;           // [0,1)
        float u = f * 2.0f + (-0.99999994f);            // lo + f*(hi-lo)
        u = fmaxf(-0.99999994f, u);
        z = 1.41421354f * erfinv_xla(u);
    }
    float noisy = cl + z * stdv;

    __shared__ float s_noisy[128], s_clean[128], s_std[128];
    __shared__ float s_thrin[B_], s_throut[B_];
    __shared__ float s_load[E_], s_imp[E_];
    s_noisy[tid] = noisy; s_clean[tid] = cl; s_std[tid] = stdv;
    if (tid < E_) { s_load[tid] = 0.0f; s_imp[tid] = 0.0f; }
    __syncthreads();

    if (tid < B_) {
        float m1 = -3.0e38f, m2 = -3.0e38f;
        int i1 = 0;
        for (int ee = 0; ee < E_; ee++) {
            float val = s_noisy[tid * 8 + ee];
            if (val > m1) { m2 = m1; m1 = val; i1 = ee; }
            else if (val > m2) { m2 = val; }
        }
        g_sel[tid] = i1;
        s_thrin[tid] = m2;    // 2nd largest (top_logits[:, K_TOP])
        s_throut[tid] = m1;   // largest     (top_logits[:, K_TOP-1])
        atomicAdd(&s_imp[i1], 1.0f);   // gate value is exactly 1.0f in fp32
    }
    __syncthreads();

    {
        float thr = (noisy > s_thrin[b]) ? s_thrin[b] : s_throut[b];
        float arg = ((cl - thr) / stdv) / 1.41421354f;
        float ph = 0.5f * (1.0f + erff(arg));
        atomicAdd(&s_load[e], ph);
    }
    __syncthreads();

    if (tid == 0) {
        auto cv2 = [](const float* x) {
            float mean = 0.0f;
            for (int i = 0; i < E_; i++) mean += x[i];
            mean *= (1.0f / E_);
            float var = 0.0f;
            for (int i = 0; i < E_; i++) { float d = x[i] - mean; var += d * d; }
            var *= (1.0f / (E_ - 1));
            return var / (mean * mean + 1e-10f);
        };
        float loss = 0.01f * (cv2(s_imp) + cv2(s_load));
        if (out_size > B_ * S_ * D_) d_out[B_ * S_ * D_] = loss;
    }
}

// ---------------- K3: projections (q/k/v) for selected expert per batch ----------------
// C(256x512) = X(256x512) @ W(512x512) + bias, stored head-major [b][h][s][dk]
__global__ void proj_kernel(const float* __restrict__ q, const float* __restrict__ k,
                            const float* __restrict__ v,
                            const float* __restrict__ wq, const float* __restrict__ wk,
                            const float* __restrict__ wv,
                            const float* __restrict__ bq, const float* __restrict__ bk,
                            const float* __restrict__ bv) {
    int z = blockIdx.z;
    int b = z / 3, p = z % 3;
    const float* X = (p == 0 ? q : (p == 1 ? k : v)) + (size_t)b * S_ * D_;
    int e = g_sel[b];
    const float* W = (p == 0 ? wq : (p == 1 ? wk : wv)) + (size_t)e * D_ * D_;
    const float* bias = (p == 0 ? bq : (p == 1 ? bk : bv)) + e * D_;
    float* Out = (p == 0 ? g_qh : (p == 1 ? g_kh : g_vh));

    int bn = blockIdx.x * 64, bm = blockIdx.y * 64;
    __shared__ float As[16][64];
    __shared__ float Bs[16][64];
    int tid = threadIdx.x;
    int tx = tid & 15, ty = tid >> 4;
    float acc[4][4] = {};
    int arow = tid >> 2, acol4 = (tid & 3) * 4;
    int brow = tid >> 4, bcol4 = (tid & 15) * 4;

    for (int k0 = 0; k0 < D_; k0 += 16) {
        float4 a4 = *(const float4*)(X + (bm + arow) * D_ + k0 + acol4);
        As[acol4 + 0][arow] = a4.x; As[acol4 + 1][arow] = a4.y;
        As[acol4 + 2][arow] = a4.z; As[acol4 + 3][arow] = a4.w;
        *(float4*)&Bs[brow][bcol4] = *(const float4*)(W + (k0 + brow) * D_ + bn + bcol4);
        __syncthreads();
#pragma unroll
        for (int kk = 0; kk < 16; kk++) {
            float a[4], bb[4];
#pragma unroll
            for (int i = 0; i < 4; i++) a[i] = As[kk][ty * 4 + i];
#pragma unroll
            for (int j = 0; j < 4; j++) bb[j] = Bs[kk][tx * 4 + j];
#pragma unroll
            for (int i = 0; i < 4; i++)
#pragma unroll
                for (int j = 0; j < 4; j++) acc[i][j] = fmaf(a[i], bb[j], acc[i][j]);
        }
        __syncthreads();
    }
#pragma unroll
    for (int i = 0; i < 4; i++) {
        int s = bm + ty * 4 + i;
#pragma unroll
        for (int j = 0; j < 4; j++) {
            int n = bn + tx * 4 + j;
            int h = n >> 6, dk = n & 63;
            Out[((b * H_ + h) * S_ + s) * DK_ + dk] = acc[i][j] + bias[n];
        }
    }
}

// ---------------- K4: scores = qh @ kh^T / 8, masked ----------------
__global__ void scores_kernel(const int* __restrict__ mask) {
    int z = blockIdx.z;                 // b*H + h
    const float* A = g_qh + (size_t)z * S_ * DK_;
    const float* Bm = g_kh + (size_t)z * S_ * DK_;
    int bn = blockIdx.x * 64, bm = blockIdx.y * 64;
    __shared__ float As[16][64];
    __shared__ float Bs[16][64];
    int tid = threadIdx.x;
    int tx = tid & 15, ty = tid >> 4;
    float acc[4][4] = {};
    int row = tid >> 2, col4 = (tid & 3) * 4;

    for (int k0 = 0; k0 < DK_; k0 += 16) {
        float4 a4 = *(const float4*)(A + (bm + row) * DK_ + k0 + col4);
        As[col4 + 0][row] = a4.x; As[col4 + 1][row] = a4.y;
        As[col4 + 2][row] = a4.z; As[col4 + 3][row] = a4.w;
        float4 b4 = *(const float4*)(Bm + (bn + row) * DK_ + k0 + col4);
        Bs[col4 + 0][row] = b4.x; Bs[col4 + 1][row] = b4.y;
        Bs[col4 + 2][row] = b4.z; Bs[col4 + 3][row] = b4.w;
        __syncthreads();
#pragma unroll
        for (int kk = 0; kk < 16; kk++) {
            float a[4], bb[4];
#pragma unroll
            for (int i = 0; i < 4; i++) a[i] = As[kk][ty * 4 + i];
#pragma unroll
            for (int j = 0; j < 4; j++) bb[j] = Bs[kk][tx * 4 + j];
#pragma unroll
            for (int i = 0; i < 4; i++)
#pragma unroll
                for (int j = 0; j < 4; j++) acc[i][j] = fmaf(a[i], bb[j], acc[i][j]);
        }
        __syncthreads();
    }
    float* outp = g_sc + (size_t)z * S_ * S_;
#pragma unroll
    for (int i = 0; i < 4; i++) {
        int qs = bm + ty * 4 + i;
#pragma unroll
        for (int j = 0; j < 4; j++) {
            int ks = bn + tx * 4 + j;
            float val = acc[i][j] * 0.125f;
            if (mask[qs * S_ + ks] == 0) val = -1000000000.0f;
            outp[qs * S_ + ks] = val;
        }
    }
}

// ---------------- K5: row softmax (warp per row) ----------------
__global__ void softmax_kernel() {
    int warp = threadIdx.x >> 5, lane = threadIdx.x & 31;
    int r = blockIdx.x * 8 + warp;                    // 32768 rows
    float* row = g_sc + (size_t)r * S_;
    float vals[8];
#pragma unroll
    for (int i = 0; i < 8; i++) vals[i] = row[i * 32 + lane];
    float m = vals[0];
#pragma unroll
    for (int i = 1; i < 8; i++) m = fmaxf(m, vals[i]);
#pragma unroll
    for (int off = 16; off > 0; off >>= 1) m = fmaxf(m, __shfl_xor_sync(0xffffffffu, m, off));
    float sum = 0.0f;
#pragma unroll
    for (int i = 0; i < 8; i++) { vals[i] = expf(vals[i] - m); sum += vals[i]; }
#pragma unroll
    for (int off = 16; off > 0; off >>= 1) sum += __shfl_xor_sync(0xffffffffu, sum, off);
    float inv = 1.0f / sum;
#pragma unroll
    for (int i = 0; i < 8; i++) row[i * 32 + lane] = vals[i] * inv;
}

// ---------------- K6: ctx = attn @ vh (per b,h) ----------------
__global__ void av_kernel() {
    int z = blockIdx.z;                 // b*H + h
    int b = z >> 3, h = z & 7;
    const float* A = g_sc + (size_t)z * S_ * S_;     // 256 x 256
    const float* Bm = g_vh + (size_t)z * S_ * DK_;   // 256 x 64
    int bm = blockIdx.y * 64;                        // bn = 0, N = 64
    __shared__ float As[16][64];
    __shared__ float Bs[16][64];
    int tid = threadIdx.x;
    int tx = tid & 15, ty = tid >> 4;
    float acc[4][4] = {};
    int arow = tid >> 2, acol4 = (tid & 3) * 4;
    int brow = tid >> 4, bcol4 = (tid & 15) * 4;

    for (int k0 = 0; k0 < S_; k0 += 16) {
        float4 a4 = *(const float4*)(A + (bm + arow) * S_ + k0 + acol4);
        As[acol4 + 0][arow] = a4.x; As[acol4 + 1][arow] = a4.y;
        As[acol4 + 2][arow] = a4.z; As[acol4 + 3][arow] = a4.w;
        *(float4*)&Bs[brow][bcol4] = *(const float4*)(Bm + (k0 + brow) * DK_ + bcol4);
        __syncthreads();
#pragma unroll
        for (int kk = 0; kk < 16; kk++) {
            float a[4], bb[4];
#pragma unroll
            for (int i = 0; i < 4; i++) a[i] = As[kk][ty * 4 + i];
#pragma unroll
            for (int j = 0; j < 4; j++) bb[j] = Bs[kk][tx * 4 + j];
#pragma unroll
            for (int i = 0; i < 4; i++)
#pragma unroll
                for (int j = 0; j < 4; j++) acc[i][j] = fmaf(a[i], bb[j], acc[i][j]);
        }
        __syncthreads();
    }
#pragma unroll
    for (int i = 0; i < 4; i++) {
        int s = bm + ty * 4 + i;
#pragma unroll
        for (int j = 0; j < 4; j++) {
            int dk = tx * 4 + j;
            g_ctx[((size_t)b * S_ + s) * D_ + h * DK_ + dk] = acc[i][j];
        }
    }
}

// ---------------- K7: out = ctx @ wo + bo  (== attn_output, see theory) ----------------
__global__ void final_kernel(const float* __restrict__ wo, const float* __restrict__ bo,
                             float* __restrict__ out) {
    int b = blockIdx.z;
    const float* A = g_ctx + (size_t)b * S_ * D_;
    int e = g_sel[b];
    const float* W = wo + (size_t)e * D_ * D_;
    const float* bias = bo + e * D_;
    int bn = blockIdx.x * 64, bm = blockIdx.y * 64;
    __shared__ float As[16][64];
    __shared__ float Bs[16][64];
    int tid = threadIdx.x;
    int tx = tid & 15, ty = tid >> 4;
    float acc[4][4] = {};
    int arow = tid >> 2, acol4 = (tid & 3) * 4;
    int brow = tid >> 4, bcol4 = (tid & 15) * 4;

    for (int k0 = 0; k0 < D_; k0 += 16) {
        float4 a4 = *(const float4*)(A + (bm + arow) * D_ + k0 + acol4);
        As[acol4 + 0][arow] = a4.x; As[acol4 + 1][arow] = a4.y;
        As[acol4 + 2][arow] = a4.z; As[acol4 + 3][arow] = a4.w;
        *(float4*)&Bs[brow][bcol4] = *(const float4*)(W + (k0 + brow) * D_ + bn + bcol4);
        __syncthreads();
#pragma unroll
        for (int kk = 0; kk < 16; kk++) {
            float a[4], bb[4];
#pragma unroll
            for (int i = 0; i < 4; i++) a[i] = As[kk][ty * 4 + i];
#pragma unroll
            for (int j = 0; j < 4; j++) bb[j] = Bs[kk][tx * 4 + j];
#pragma unroll
            for (int i = 0; i < 4; i++)
#pragma unroll
                for (int j = 0; j < 4; j++) acc[i][j] = fmaf(a[i], bb[j], acc[i][j]);
        }
        __syncthreads();
    }
#pragma unroll
    for (int i = 0; i < 4; i++) {
        int s = bm + ty * 4 + i;
#pragma unroll
        for (int j = 0; j < 4; j++) {
            int n = bn + tx * 4 + j;
            out[((size_t)b * S_ + s) * D_ + n] = acc[i][j] + bias[n];
        }
    }
}

// ---------------- launch ----------------
extern "C" void kernel_launch(void* const* d_in, const int* in_sizes, int n_in,
                              void* d_out, int out_size) {
    const float* q    = (const float*)d_in[0];
    const float* k    = (const float*)d_in[1];
    const float* v    = (const float*)d_in[2];
    const int*   mask = (const int*)  d_in[3];
    const float* wg   = (const float*)d_in[4];
    const float* wn   = (const float*)d_in[5];
    const float* wq   = (const float*)d_in[6];
    const float* bq   = (const float*)d_in[7];
    const float* wk   = (const float*)d_in[8];
    const float* bk   = (const float*)d_in[9];
    const float* wv   = (const float*)d_in[10];
    const float* bv   = (const float*)d_in[11];
    const float* wo   = (const float*)d_in[12];
    const float* bo   = (const float*)d_in[13];
    float* out = (float*)d_out;

    xsum_kernel<<<dim3(B_, 8), 512>>>(q);
    gating_kernel<<<1, 128>>>(wg, wn, out, out_size);
    proj_kernel<<<dim3(8, 4, B_ * 3), 256>>>(q, k, v, wq, wk, wv, bq, bk, bv);
    scores_kernel<<<dim3(4, 4, B_ * H_), 256>>>(mask);
    softmax_kernel<<<B_ * H_ * S_ / 8, 256>>>();
    av_kernel<<<dim3(1, 4, B_ * H_), 256>>>();
    final_kernel<<<dim3(8, 4, B_), 256>>>(wo, bo, out);
}

// round 3
// speedup vs baseline: 1.0820x; 1.0820x over previous
#include <cuda_runtime.h>
#include <cstdint>

#define E_  8
#define H_  8
#define D_  512
#define B_  16
#define S_  256
#define DK_ 64

// ---------------- scratch ----------------
__device__ float g_xsum_part[B_ * 8 * D_];
__device__ int   g_sel[B_];
__device__ float g_qh[B_ * H_ * DK_ * S_];          // [b][h][dk][s]  (transposed)
__device__ float g_kh[B_ * H_ * DK_ * S_];          // [b][h][dk][kcol] (transposed)
__device__ float g_vh[B_ * H_ * S_ * DK_];          // [b][h][s][dk]
__device__ float g_ctx[B_ * S_ * D_];

// ---------------- threefry2x32 (JAX partitionable, key=(0,42)) ----------------
__device__ __forceinline__ uint32_t rotl32(uint32_t x, int r) {
    return (x << r) | (x >> (32 - r));
}

__device__ void threefry2x32(uint32_t k0, uint32_t k1, uint32_t c0, uint32_t c1,
                             uint32_t* o0, uint32_t* o1) {
    uint32_t ks2 = k0 ^ k1 ^ 0x1BD11BDAu;
    uint32_t x0 = c0 + k0;
    uint32_t x1 = c1 + k1;
    const int R0[4] = {13, 15, 26, 6};
    const int R1[4] = {17, 29, 16, 24};
#pragma unroll
    for (int i = 0; i < 4; i++) { x0 += x1; x1 = rotl32(x1, R0[i]); x1 ^= x0; }
    x0 += k1;  x1 += ks2 + 1u;
#pragma unroll
    for (int i = 0; i < 4; i++) { x0 += x1; x1 = rotl32(x1, R1[i]); x1 ^= x0; }
    x0 += ks2; x1 += k0 + 2u;
#pragma unroll
    for (int i = 0; i < 4; i++) { x0 += x1; x1 = rotl32(x1, R0[i]); x1 ^= x0; }
    x0 += k0;  x1 += k1 + 3u;
#pragma unroll
    for (int i = 0; i < 4; i++) { x0 += x1; x1 = rotl32(x1, R1[i]); x1 ^= x0; }
    x0 += k1;  x1 += ks2 + 4u;
#pragma unroll
    for (int i = 0; i < 4; i++) { x0 += x1; x1 = rotl32(x1, R0[i]); x1 ^= x0; }
    x0 += ks2; x1 += k0 + 5u;
    *o0 = x0; *o1 = x1;
}

__device__ float erfinv_xla(float x) {
    float w = -log1pf(-x * x);
    float p;
    if (w < 5.0f) {
        w -= 2.5f;
        p = 2.81022636e-08f;
        p = fmaf(p, w, 3.43273939e-07f);
        p = fmaf(p, w, -3.5233877e-06f);
        p = fmaf(p, w, -4.39150654e-06f);
        p = fmaf(p, w, 0.00021858087f);
        p = fmaf(p, w, -0.00125372503f);
        p = fmaf(p, w, -0.00417768164f);
        p = fmaf(p, w, 0.246640727f);
        p = fmaf(p, w, 1.50140941f);
    } else {
        w = sqrtf(w) - 3.0f;
        p = -0.000200214257f;
        p = fmaf(p, w, 0.000100950558f);
        p = fmaf(p, w, 0.00134934322f);
        p = fmaf(p, w, -0.00367342844f);
        p = fmaf(p, w, 0.00573950773f);
        p = fmaf(p, w, -0.0076224613f);
        p = fmaf(p, w, 0.00943887047f);
        p = fmaf(p, w, 1.00167406f);
        p = fmaf(p, w, 2.83297682f);
    }
    return p * x;
}

// ---------------- K1: partial sums of q over S ----------------
__global__ void xsum_kernel(const float* __restrict__ q) {
    int b = blockIdx.x, part = blockIdx.y, d = threadIdx.x;
    const float* p = q + ((size_t)b * S_ + part * 32) * D_ + d;
    float acc = 0.0f;
#pragma unroll
    for (int s = 0; s < 32; s++) acc += p[s * D_];
    g_xsum_part[(b * 8 + part) * D_ + d] = acc;
}

// ---------------- K2: gating ----------------
__global__ void gating_kernel(const float* __restrict__ wg,
                              const float* __restrict__ wn,
                              float* __restrict__ d_out, int out_size) {
    int tid = threadIdx.x;
    int b = tid >> 3, e = tid & 7;

    float cl = 0.0f, rn = 0.0f;
    for (int i = 0; i < D_; i++) {
        float xs = 0.0f;
#pragma unroll
        for (int p = 0; p < 8; p++) xs += g_xsum_part[(b * 8 + p) * D_ + i];
        cl = fmaf(xs, wg[i * E_ + e], cl);
        rn = fmaf(xs, wn[i * E_ + e], rn);
    }

    float sp = fmaxf(rn, 0.0f) + log1pf(expf(-fabsf(rn)));
    float stdv = sp + 0.01f;

    float z;
    {
        uint32_t j = (uint32_t)tid;
        uint32_t o0, o1;
        threefry2x32(0u, 42u, 0u, j, &o0, &o1);
        uint32_t bits = o0 ^ o1;
        uint32_t fb = (bits >> 9) | 0x3f800000u;
        float f = __uint_as_float(fb) - 1.0f;
        float u = f * 2.0f + (-0.99999994f);
        u = fmaxf(-0.99999994f, u);
        z = 1.41421354f * erfinv_xla(u);
    }
    float noisy = cl + z * stdv;

    __shared__ float s_noisy[128];
    __shared__ float s_thrin[B_], s_throut[B_];
    __shared__ float s_load[E_], s_imp[E_];
    s_noisy[tid] = noisy;
    if (tid < E_) { s_load[tid] = 0.0f; s_imp[tid] = 0.0f; }
    __syncthreads();

    if (tid < B_) {
        float m1 = -3.0e38f, m2 = -3.0e38f;
        int i1 = 0;
        for (int ee = 0; ee < E_; ee++) {
            float val = s_noisy[tid * 8 + ee];
            if (val > m1) { m2 = m1; m1 = val; i1 = ee; }
            else if (val > m2) { m2 = val; }
        }
        g_sel[tid] = i1;
        s_thrin[tid] = m2;
        s_throut[tid] = m1;
        atomicAdd(&s_imp[i1], 1.0f);
    }
    __syncthreads();

    {
        float thr = (noisy > s_thrin[b]) ? s_thrin[b] : s_throut[b];
        float arg = ((cl - thr) / stdv) / 1.41421354f;
        float ph = 0.5f * (1.0f + erff(arg));
        atomicAdd(&s_load[e], ph);
    }
    __syncthreads();

    if (tid == 0) {
        auto cv2 = [](const float* x) {
            float mean = 0.0f;
            for (int i = 0; i < E_; i++) mean += x[i];
            mean *= (1.0f / E_);
            float var = 0.0f;
            for (int i = 0; i < E_; i++) { float d = x[i] - mean; var += d * d; }
            var *= (1.0f / (E_ - 1));
            return var / (mean * mean + 1e-10f);
        };
        float loss = 0.01f * (cv2(s_imp) + cv2(s_load));
        if (out_size > B_ * S_ * D_) d_out[B_ * S_ * D_] = loss;
    }
}

// ---------------- K3: projections, 128x128 tile, 8x8 micro, double-buffered ----------------
__global__ __launch_bounds__(256) void proj_kernel(
        const float* __restrict__ q, const float* __restrict__ k,
        const float* __restrict__ v,
        const float* __restrict__ wq, const float* __restrict__ wk,
        const float* __restrict__ wv,
        const float* __restrict__ bq, const float* __restrict__ bk,
        const float* __restrict__ bv) {
    int z = blockIdx.z;
    int b = z / 3, p = z % 3;
    const float* X = (p == 0 ? q : (p == 1 ? k : v)) + (size_t)b * S_ * D_;
    int e = g_sel[b];
    const float* W = (p == 0 ? wq : (p == 1 ? wk : wv)) + (size_t)e * D_ * D_;
    const float* bias = (p == 0 ? bq : (p == 1 ? bk : bv)) + e * D_;
    float* Out = (p == 0 ? g_qh : (p == 1 ? g_kh : g_vh));

    int bn = blockIdx.x * 128, bm = blockIdx.y * 128;
    __shared__ float As[2][16][128];
    __shared__ float Bs[2][16][128];
    int tid = threadIdx.x;
    int tx = tid & 15, ty = tid >> 4;
    int arow = tid >> 1, akq = (tid & 1) * 8;
    int bkr = tid >> 4, bc4 = (tid & 15) * 4;

    const float* Xr = X + (size_t)(bm + arow) * D_;
    float4 a0, a1, b0, b1;
    a0 = *(const float4*)(Xr + akq);
    a1 = *(const float4*)(Xr + akq + 4);
    b0 = *(const float4*)(W + (size_t)bkr * D_ + bn + bc4);
    b1 = *(const float4*)(W + (size_t)bkr * D_ + bn + bc4 + 64);
    As[0][akq + 0][arow] = a0.x; As[0][akq + 1][arow] = a0.y;
    As[0][akq + 2][arow] = a0.z; As[0][akq + 3][arow] = a0.w;
    As[0][akq + 4][arow] = a1.x; As[0][akq + 5][arow] = a1.y;
    As[0][akq + 6][arow] = a1.z; As[0][akq + 7][arow] = a1.w;
    *(float4*)&Bs[0][bkr][bc4] = b0;
    *(float4*)&Bs[0][bkr][bc4 + 64] = b1;
    __syncthreads();

    float acc[8][8] = {};
    for (int t = 0; t < 32; t++) {
        int buf = t & 1;
        if (t < 31) {
            int k0 = (t + 1) * 16;
            a0 = *(const float4*)(Xr + k0 + akq);
            a1 = *(const float4*)(Xr + k0 + akq + 4);
            b0 = *(const float4*)(W + (size_t)(k0 + bkr) * D_ + bn + bc4);
            b1 = *(const float4*)(W + (size_t)(k0 + bkr) * D_ + bn + bc4 + 64);
        }
#pragma unroll
        for (int kk = 0; kk < 16; kk++) {
            float4 x0 = *(const float4*)&As[buf][kk][ty * 8];
            float4 x1 = *(const float4*)&As[buf][kk][ty * 8 + 4];
            float4 y0 = *(const float4*)&Bs[buf][kk][tx * 8];
            float4 y1 = *(const float4*)&Bs[buf][kk][tx * 8 + 4];
            float a[8] = {x0.x, x0.y, x0.z, x0.w, x1.x, x1.y, x1.z, x1.w};
            float bb[8] = {y0.x, y0.y, y0.z, y0.w, y1.x, y1.y, y1.z, y1.w};
#pragma unroll
            for (int i = 0; i < 8; i++)
#pragma unroll
                for (int j = 0; j < 8; j++) acc[i][j] = fmaf(a[i], bb[j], acc[i][j]);
        }
        if (t < 31) {
            int nb = buf ^ 1;
            As[nb][akq + 0][arow] = a0.x; As[nb][akq + 1][arow] = a0.y;
            As[nb][akq + 2][arow] = a0.z; As[nb][akq + 3][arow] = a0.w;
            As[nb][akq + 4][arow] = a1.x; As[nb][akq + 5][arow] = a1.y;
            As[nb][akq + 6][arow] = a1.z; As[nb][akq + 7][arow] = a1.w;
            *(float4*)&Bs[nb][bkr][bc4] = b0;
            *(float4*)&Bs[nb][bkr][bc4 + 64] = b1;
            __syncthreads();
        }
    }

    // epilogue
    int n0 = bn + tx * 8;            // 8 contiguous n within one head (8 | 64)
    int h = n0 >> 6;
    int dk0 = n0 & 63;
    int s0 = bm + ty * 8;
    if (p < 2) {
        // transposed per head: [b][h][dk][s]
#pragma unroll
        for (int j = 0; j < 8; j++) {
            float bj = bias[n0 + j];
            float* dst = Out + (((size_t)(b * H_ + h) * DK_ + dk0 + j) * S_ + s0);
            float4 v0 = make_float4(acc[0][j] + bj, acc[1][j] + bj, acc[2][j] + bj, acc[3][j] + bj);
            float4 v1 = make_float4(acc[4][j] + bj, acc[5][j] + bj, acc[6][j] + bj, acc[7][j] + bj);
            *(float4*)(dst) = v0;
            *(float4*)(dst + 4) = v1;
        }
    } else {
        // v: [b][h][s][dk]
#pragma unroll
        for (int i = 0; i < 8; i++) {
            float* dst = Out + (((size_t)(b * H_ + h) * S_ + s0 + i) * DK_ + dk0);
            float4 v0 = make_float4(acc[i][0] + bias[n0 + 0], acc[i][1] + bias[n0 + 1],
                                    acc[i][2] + bias[n0 + 2], acc[i][3] + bias[n0 + 3]);
            float4 v1 = make_float4(acc[i][4] + bias[n0 + 4], acc[i][5] + bias[n0 + 5],
                                    acc[i][6] + bias[n0 + 6], acc[i][7] + bias[n0 + 7]);
            *(float4*)(dst) = v0;
            *(float4*)(dst + 4) = v1;
        }
    }
}

// ---------------- K4: fused attention (scores + mask + softmax + AV) ----------------
// one block per (b,h); dynamic smem: Kt[64][256] | Vs[256][64] | Ps[64][256] | Qt[64][64]
__global__ __launch_bounds__(256) void fused_attn_kernel(const int* __restrict__ mask) {
    extern __shared__ float sm[];
    float* Kt = sm;                    // 16384 floats
    float* Vs = sm + 16384;            // 16384
    float* Ps = sm + 32768;            // 16384
    float* Qt = sm + 49152;            // 4096

    int z = blockIdx.x;
    int b = z >> 3, h = z & 7;
    int tid = threadIdx.x;

    // load K (already [dk][kcol]) and V ([s][dk]) straight
    const float4* ksrc = (const float4*)(g_kh + (size_t)z * 16384);
    const float4* vsrc = (const float4*)(g_vh + (size_t)z * 16384);
    float4* kdst = (float4*)Kt;
    float4* vdst = (float4*)Vs;
#pragma unroll
    for (int i = 0; i < 16; i++) {
        kdst[tid + i * 256] = ksrc[tid + i * 256];
        vdst[tid + i * 256] = vsrc[tid + i * 256];
    }

    int ty = tid >> 5, txx = tid & 31;      // GEMM1 layout: 8 x 32
    int ty2 = tid >> 4, tx2 = tid & 15;     // GEMM2 layout: 16 x 16

    for (int qt = 0; qt < 4; qt++) {
        // load Q tile: g_qh [b][h][dk][s], take s in [qt*64, qt*64+64) -> Qt[dk][0..63]
        const float* qsrc = g_qh + (size_t)z * 16384 + qt * 64;
#pragma unroll
        for (int i = 0; i < 4; i++) {
            int lin = tid + i * 256;        // 0..1023 -> dk = lin/16, c4 = (lin%16)*4
            int dk = lin >> 4, c = (lin & 15) * 4;
            *(float4*)&Qt[dk * 64 + c] = *(const float4*)(qsrc + (size_t)dk * S_ + c);
        }
        __syncthreads();   // Qt ready; also ensures prior GEMM2 done reading Ps

        // GEMM1: scores(64x256) = Qt^T(64xdk) @ Kt(dk x 256); thread: rows ty*8.., cols txx*8..
        float p[8][8] = {};
#pragma unroll 4
        for (int dk = 0; dk < 64; dk++) {
            float4 x0 = *(const float4*)&Qt[dk * 64 + ty * 8];
            float4 x1 = *(const float4*)&Qt[dk * 64 + ty * 8 + 4];
            float4 y0 = *(const float4*)&Kt[dk * 256 + txx * 8];
            float4 y1 = *(const float4*)&Kt[dk * 256 + txx * 8 + 4];
            float a[8] = {x0.x, x0.y, x0.z, x0.w, x1.x, x1.y, x1.z, x1.w};
            float bb[8] = {y0.x, y0.y, y0.z, y0.w, y1.x, y1.y, y1.z, y1.w};
#pragma unroll
            for (int i = 0; i < 8; i++)
#pragma unroll
                for (int j = 0; j < 8; j++) p[i][j] = fmaf(a[i], bb[j], p[i][j]);
        }

        // scale + mask + softmax (row = warp: ty fixed -> lanes cover all 256 cols)
#pragma unroll
        for (int i = 0; i < 8; i++) {
            int r = qt * 64 + ty * 8 + i;
            int4 m0 = *(const int4*)&mask[r * S_ + txx * 8];
            int4 m1 = *(const int4*)&mask[r * S_ + txx * 8 + 4];
            p[i][0] = (m0.x == 0) ? -1e9f : p[i][0] * 0.125f;
            p[i][1] = (m0.y == 0) ? -1e9f : p[i][1] * 0.125f;
            p[i][2] = (m0.z == 0) ? -1e9f : p[i][2] * 0.125f;
            p[i][3] = (m0.w == 0) ? -1e9f : p[i][3] * 0.125f;
            p[i][4] = (m1.x == 0) ? -1e9f : p[i][4] * 0.125f;
            p[i][5] = (m1.y == 0) ? -1e9f : p[i][5] * 0.125f;
            p[i][6] = (m1.z == 0) ? -1e9f : p[i][6] * 0.125f;
            p[i][7] = (m1.w == 0) ? -1e9f : p[i][7] * 0.125f;

            float mx = p[i][0];
#pragma unroll
            for (int j = 1; j < 8; j++) mx = fmaxf(mx, p[i][j]);
#pragma unroll
            for (int off = 16; off > 0; off >>= 1)
                mx = fmaxf(mx, __shfl_xor_sync(0xffffffffu, mx, off));
            float sum = 0.0f;
#pragma unroll
            for (int j = 0; j < 8; j++) { p[i][j] = expf(p[i][j] - mx); sum += p[i][j]; }
#pragma unroll
            for (int off = 16; off > 0; off >>= 1)
                sum += __shfl_xor_sync(0xffffffffu, sum, off);
            float inv = 1.0f / sum;
#pragma unroll
            for (int j = 0; j < 8; j++) p[i][j] *= inv;
        }

        // write P
#pragma unroll
        for (int i = 0; i < 8; i++) {
            *(float4*)&Ps[(ty * 8 + i) * 256 + txx * 8] =
                make_float4(p[i][0], p[i][1], p[i][2], p[i][3]);
            *(float4*)&Ps[(ty * 8 + i) * 256 + txx * 8 + 4] =
                make_float4(p[i][4], p[i][5], p[i][6], p[i][7]);
        }
        __syncthreads();

        // GEMM2: ctx(64x64) = Ps(64x256) @ Vs(256x64); thread: rows ty2*4.., cols tx2*4..
        float c2[4][4] = {};
#pragma unroll 2
        for (int kc = 0; kc < 256; kc += 4) {
            float4 av[4], bv[4];
#pragma unroll
            for (int i = 0; i < 4; i++) av[i] = *(const float4*)&Ps[(ty2 * 4 + i) * 256 + kc];
#pragma unroll
            for (int t = 0; t < 4; t++) bv[t] = *(const float4*)&Vs[(kc + t) * 64 + tx2 * 4];
            float aa[4][4] = {{av[0].x, av[0].y, av[0].z, av[0].w},
                              {av[1].x, av[1].y, av[1].z, av[1].w},
                              {av[2].x, av[2].y, av[2].z, av[2].w},
                              {av[3].x, av[3].y, av[3].z, av[3].w}};
            float bb2[4][4] = {{bv[0].x, bv[0].y, bv[0].z, bv[0].w},
                               {bv[1].x, bv[1].y, bv[1].z, bv[1].w},
                               {bv[2].x, bv[2].y, bv[2].z, bv[2].w},
                               {bv[3].x, bv[3].y, bv[3].z, bv[3].w}};
#pragma unroll
            for (int t = 0; t < 4; t++)
#pragma unroll
                for (int i = 0; i < 4; i++)
#pragma unroll
                    for (int j = 0; j < 4; j++)
                        c2[i][j] = fmaf(aa[i][t], bb2[t][j], c2[i][j]);
        }

        // write ctx
#pragma unroll
        for (int i = 0; i < 4; i++) {
            int s = qt * 64 + ty2 * 4 + i;
            *(float4*)&g_ctx[((size_t)b * S_ + s) * D_ + h * DK_ + tx2 * 4] =
                make_float4(c2[i][0], c2[i][1], c2[i][2], c2[i][3]);
        }
    }
}

// ---------------- K5: final projection, 128x128 tile ----------------
__global__ __launch_bounds__(256) void final_kernel(const float* __restrict__ wo,
                                                    const float* __restrict__ bo,
                                                    float* __restrict__ out) {
    int b = blockIdx.z;
    const float* A = g_ctx + (size_t)b * S_ * D_;
    int e = g_sel[b];
    const float* W = wo + (size_t)e * D_ * D_;
    const float* bias = bo + e * D_;

    int bn = blockIdx.x * 128, bm = blockIdx.y * 128;
    __shared__ float As[2][16][128];
    __shared__ float Bs[2][16][128];
    int tid = threadIdx.x;
    int tx = tid & 15, ty = tid >> 4;
    int arow = tid >> 1, akq = (tid & 1) * 8;
    int bkr = tid >> 4, bc4 = (tid & 15) * 4;

    const float* Xr = A + (size_t)(bm + arow) * D_;
    float4 a0, a1, b0, b1;
    a0 = *(const float4*)(Xr + akq);
    a1 = *(const float4*)(Xr + akq + 4);
    b0 = *(const float4*)(W + (size_t)bkr * D_ + bn + bc4);
    b1 = *(const float4*)(W + (size_t)bkr * D_ + bn + bc4 + 64);
    As[0][akq + 0][arow] = a0.x; As[0][akq + 1][arow] = a0.y;
    As[0][akq + 2][arow] = a0.z; As[0][akq + 3][arow] = a0.w;
    As[0][akq + 4][arow] = a1.x; As[0][akq + 5][arow] = a1.y;
    As[0][akq + 6][arow] = a1.z; As[0][akq + 7][arow] = a1.w;
    *(float4*)&Bs[0][bkr][bc4] = b0;
    *(float4*)&Bs[0][bkr][bc4 + 64] = b1;
    __syncthreads();

    float acc[8][8] = {};
    for (int t = 0; t < 32; t++) {
        int buf = t & 1;
        if (t < 31) {
            int k0 = (t + 1) * 16;
            a0 = *(const float4*)(Xr + k0 + akq);
            a1 = *(const float4*)(Xr + k0 + akq + 4);
            b0 = *(const float4*)(W + (size_t)(k0 + bkr) * D_ + bn + bc4);
            b1 = *(const float4*)(W + (size_t)(k0 + bkr) * D_ + bn + bc4 + 64);
        }
#pragma unroll
        for (int kk = 0; kk < 16; kk++) {
            float4 x0 = *(const float4*)&As[buf][kk][ty * 8];
            float4 x1 = *(const float4*)&As[buf][kk][ty * 8 + 4];
            float4 y0 = *(const float4*)&Bs[buf][kk][tx * 8];
            float4 y1 = *(const float4*)&Bs[buf][kk][tx * 8 + 4];
            float a[8] = {x0.x, x0.y, x0.z, x0.w, x1.x, x1.y, x1.z, x1.w};
            float bb[8] = {y0.x, y0.y, y0.z, y0.w, y1.x, y1.y, y1.z, y1.w};
#pragma unroll
            for (int i = 0; i < 8; i++)
#pragma unroll
                for (int j = 0; j < 8; j++) acc[i][j] = fmaf(a[i], bb[j], acc[i][j]);
        }
        if (t < 31) {
            int nb = buf ^ 1;
            As[nb][akq + 0][arow] = a0.x; As[nb][akq + 1][arow] = a0.y;
            As[nb][akq + 2][arow] = a0.z; As[nb][akq + 3][arow] = a0.w;
            As[nb][akq + 4][arow] = a1.x; As[nb][akq + 5][arow] = a1.y;
            As[nb][akq + 6][arow] = a1.z; As[nb][akq + 7][arow] = a1.w;
            *(float4*)&Bs[nb][bkr][bc4] = b0;
            *(float4*)&Bs[nb][bkr][bc4 + 64] = b1;
            __syncthreads();
        }
    }

    int n0 = bn + tx * 8;
    int s0 = bm + ty * 8;
#pragma unroll
    for (int i = 0; i < 8; i++) {
        float* dst = out + ((size_t)b * S_ + s0 + i) * D_ + n0;
        float4 v0 = make_float4(acc[i][0] + bias[n0 + 0], acc[i][1] + bias[n0 + 1],
                                acc[i][2] + bias[n0 + 2], acc[i][3] + bias[n0 + 3]);
        float4 v1 = make_float4(acc[i][4] + bias[n0 + 4], acc[i][5] + bias[n0 + 5],
                                acc[i][6] + bias[n0 + 6], acc[i][7] + bias[n0 + 7]);
        *(float4*)(dst) = v0;
        *(float4*)(dst + 4) = v1;
    }
}

// ---------------- launch ----------------
extern "C" void kernel_launch(void* const* d_in, const int* in_sizes, int n_in,
                              void* d_out, int out_size) {
    const float* q    = (const float*)d_in[0];
    const float* k    = (const float*)d_in[1];
    const float* v    = (const float*)d_in[2];
    const int*   mask = (const int*)  d_in[3];
    const float* wg   = (const float*)d_in[4];
    const float* wn   = (const float*)d_in[5];
    const float* wq   = (const float*)d_in[6];
    const float* bq   = (const float*)d_in[7];
    const float* wk   = (const float*)d_in[8];
    const float* bk   = (const float*)d_in[9];
    const float* wv   = (const float*)d_in[10];
    const float* bv   = (const float*)d_in[11];
    const float* wo   = (const float*)d_in[12];
    const float* bo   = (const float*)d_in[13];
    float* out = (float*)d_out;

    static_assert(sizeof(float) == 4, "");
    const int attn_smem = (16384 * 3 + 4096) * 4;   // 212992 bytes
    cudaFuncSetAttribute(fused_attn_kernel,
                         cudaFuncAttributeMaxDynamicSharedMemorySize, attn_smem);

    xsum_kernel<<<dim3(B_, 8), 512>>>(q);
    gating_kernel<<<1, 128>>>(wg, wn, out, out_size);
    proj_kernel<<<dim3(4, 2, B_ * 3), 256>>>(q, k, v, wq, wk, wv, bq, bk, bv);
    fused_attn_kernel<<<B_ * H_, 256, attn_smem>>>(mask);
    final_kernel<<<dim3(4, 2, B_), 256>>>(wo, bo, out);
}

// round 5
// speedup vs baseline: 1.8474x; 1.7074x over previous
#include <cuda_runtime.h>
#include <cstdint>

#define E_  8
#define H_  8
#define D_  512
#define B_  16
#define S_  256
#define DK_ 64

// ---------------- scratch ----------------
__device__ float g_xsum[B_ * D_];
__device__ int   g_sel[B_];
__device__ float g_qh[B_ * H_ * DK_ * S_];          // [b][h][dk][s]
__device__ float g_kh[B_ * H_ * DK_ * S_];          // [b][h][dk][kcol]
__device__ float g_vh[B_ * H_ * S_ * DK_];          // [b][h][s][dk]
__device__ float g_ctx[B_ * S_ * D_];

// ---------------- helpers ----------------
__device__ __forceinline__ uint32_t f2tf32(float x) {
    uint32_t r;
    asm("cvt.rna.tf32.f32 %0, %1;" : "=r"(r) : "f"(x));
    return r;
}

__device__ __forceinline__ void mma_tf32(float* c, const uint32_t* a, const uint32_t* b) {
    asm volatile(
        "mma.sync.aligned.m16n8k8.row.col.f32.tf32.tf32.f32 "
        "{%0,%1,%2,%3}, {%4,%5,%6,%7}, {%8,%9}, {%0,%1,%2,%3};"
        : "+f"(c[0]), "+f"(c[1]), "+f"(c[2]), "+f"(c[3])
        : "r"(a[0]), "r"(a[1]), "r"(a[2]), "r"(a[3]), "r"(b[0]), "r"(b[1]));
}

// ---------------- threefry2x32 (JAX partitionable, key=(0,42)) ----------------
__device__ __forceinline__ uint32_t rotl32(uint32_t x, int r) {
    return (x << r) | (x >> (32 - r));
}
__device__ void threefry2x32(uint32_t k0, uint32_t k1, uint32_t c0, uint32_t c1,
                             uint32_t* o0, uint32_t* o1) {
    uint32_t ks2 = k0 ^ k1 ^ 0x1BD11BDAu;
    uint32_t x0 = c0 + k0;
    uint32_t x1 = c1 + k1;
    const int R0[4] = {13, 15, 26, 6};
    const int R1[4] = {17, 29, 16, 24};
#pragma unroll
    for (int i = 0; i < 4; i++) { x0 += x1; x1 = rotl32(x1, R0[i]); x1 ^= x0; }
    x0 += k1;  x1 += ks2 + 1u;
#pragma unroll
    for (int i = 0; i < 4; i++) { x0 += x1; x1 = rotl32(x1, R1[i]); x1 ^= x0; }
    x0 += ks2; x1 += k0 + 2u;
#pragma unroll
    for (int i = 0; i < 4; i++) { x0 += x1; x1 = rotl32(x1, R0[i]); x1 ^= x0; }
    x0 += k0;  x1 += k1 + 3u;
#pragma unroll
    for (int i = 0; i < 4; i++) { x0 += x1; x1 = rotl32(x1, R1[i]); x1 ^= x0; }
    x0 += k1;  x1 += ks2 + 4u;
#pragma unroll
    for (int i = 0; i < 4; i++) { x0 += x1; x1 = rotl32(x1, R0[i]); x1 ^= x0; }
    x0 += ks2; x1 += k0 + 5u;
    *o0 = x0; *o1 = x1;
}

__device__ float erfinv_xla(float x) {
    float w = -log1pf(-x * x);
    float p;
    if (w < 5.0f) {
        w -= 2.5f;
        p = 2.81022636e-08f;
        p = fmaf(p, w, 3.43273939e-07f);
        p = fmaf(p, w, -3.5233877e-06f);
        p = fmaf(p, w, -4.39150654e-06f);
        p = fmaf(p, w, 0.00021858087f);
        p = fmaf(p, w, -0.00125372503f);
        p = fmaf(p, w, -0.00417768164f);
        p = fmaf(p, w, 0.246640727f);
        p = fmaf(p, w, 1.50140941f);
    } else {
        w = sqrtf(w) - 3.0f;
        p = -0.000200214257f;
        p = fmaf(p, w, 0.000100950558f);
        p = fmaf(p, w, 0.00134934322f);
        p = fmaf(p, w, -0.00367342844f);
        p = fmaf(p, w, 0.00573950773f);
        p = fmaf(p, w, -0.0076224613f);
        p = fmaf(p, w, 0.00943887047f);
        p = fmaf(p, w, 1.00167406f);
        p = fmaf(p, w, 2.83297682f);
    }
    return p * x;
}

// ---------------- K1: full xsum ----------------
__global__ void xsum_kernel(const float* __restrict__ q) {
    int b = blockIdx.x, d = threadIdx.x;
    const float* p = q + (size_t)b * S_ * D_ + d;
    float acc = 0.0f;
    for (int s = 0; s < S_; s++) acc += p[s * D_];
    g_xsum[b * D_ + d] = acc;
}

// ---------------- K2: gating ----------------
__global__ void gating_kernel(const float* __restrict__ wg,
                              const float* __restrict__ wn,
                              float* __restrict__ d_out, int out_size) {
    int tid = threadIdx.x;
    int b = tid >> 3, e = tid & 7;

    float cl = 0.0f, rn = 0.0f;
    for (int i = 0; i < D_; i++) {
        float xs = g_xsum[b * D_ + i];
        cl = fmaf(xs, wg[i * E_ + e], cl);
        rn = fmaf(xs, wn[i * E_ + e], rn);
    }

    float sp = fmaxf(rn, 0.0f) + log1pf(expf(-fabsf(rn)));
    float stdv = sp + 0.01f;

    float z;
    {
        uint32_t o0, o1;
        threefry2x32(0u, 42u, 0u, (uint32_t)tid, &o0, &o1);
        uint32_t bits = o0 ^ o1;
        uint32_t fb = (bits >> 9) | 0x3f800000u;
        float f = __uint_as_float(fb) - 1.0f;
        float u = f * 2.0f + (-0.99999994f);
        u = fmaxf(-0.99999994f, u);
        z = 1.41421354f * erfinv_xla(u);
    }
    float noisy = cl + z * stdv;

    __shared__ float s_noisy[128];
    __shared__ float s_thrin[B_], s_throut[B_];
    __shared__ float s_load[E_], s_imp[E_];
    s_noisy[tid] = noisy;
    if (tid < E_) { s_load[tid] = 0.0f; s_imp[tid] = 0.0f; }
    __syncthreads();

    if (tid < B_) {
        float m1 = -3.0e38f, m2 = -3.0e38f;
        int i1 = 0;
        for (int ee = 0; ee < E_; ee++) {
            float val = s_noisy[tid * 8 + ee];
            if (val > m1) { m2 = m1; m1 = val; i1 = ee; }
            else if (val > m2) { m2 = val; }
        }
        g_sel[tid] = i1;
        s_thrin[tid] = m2;
        s_throut[tid] = m1;
        atomicAdd(&s_imp[i1], 1.0f);
    }
    __syncthreads();

    {
        float thr = (noisy > s_thrin[b]) ? s_thrin[b] : s_throut[b];
        float arg = ((cl - thr) / stdv) / 1.41421354f;
        float ph = 0.5f * (1.0f + erff(arg));
        atomicAdd(&s_load[e], ph);
    }
    __syncthreads();

    if (tid == 0) {
        auto cv2 = [](const float* x) {
            float mean = 0.0f;
            for (int i = 0; i < E_; i++) mean += x[i];
            mean *= (1.0f / E_);
            float var = 0.0f;
            for (int i = 0; i < E_; i++) { float d = x[i] - mean; var += d * d; }
            var *= (1.0f / (E_ - 1));
            return var / (mean * mean + 1e-10f);
        };
        float loss = 0.01f * (cv2(s_imp) + cv2(s_load));
        if (out_size > B_ * S_ * D_) d_out[B_ * S_ * D_] = loss;
    }
}

// ---------------- tf32 mma.sync mainloop (128x128 block, K=512) ----------------
// smem (uint32): A bufs @0/@4608 (stride 36), B bufs @9216/@13440 (stride 132)
#define SA_ 36
#define SB_ 132
#define MMA_SMEM_BYTES ((4608 * 2 + 4224 * 2) * 4)

__device__ __forceinline__ void mma_mainloop(
        uint32_t* sm, const float* __restrict__ A, int lda,
        const float* __restrict__ W, int n0, float acc[4][4][4]) {
    const int tid = threadIdx.x;
    const int wid = tid >> 5, lane = tid & 31;
    const int wm = (wid & 1) * 64, wn = (wid >> 1) * 32;
    const int group = lane >> 2, tig = lane & 3;

    const int arow = tid >> 1, acol = (tid & 1) * 16;
    const int brow = tid >> 3, bcol = (tid & 7) * 16;

    float4 ar[4], br[4];
#pragma unroll
    for (int i = 0; i < 4; i++) {
        ar[i] = *(const float4*)(A + (size_t)arow * lda + acol + 4 * i);
        br[i] = *(const float4*)(W + (size_t)brow * D_ + n0 + bcol + 4 * i);
    }
    {
        uint32_t* da = sm + arow * SA_ + acol;
        uint32_t* db = sm + 9216 + brow * SB_ + bcol;
#pragma unroll
        for (int i = 0; i < 4; i++) {
            da[4*i+0] = f2tf32(ar[i].x); da[4*i+1] = f2tf32(ar[i].y);
            da[4*i+2] = f2tf32(ar[i].z); da[4*i+3] = f2tf32(ar[i].w);
            db[4*i+0] = f2tf32(br[i].x); db[4*i+1] = f2tf32(br[i].y);
            db[4*i+2] = f2tf32(br[i].z); db[4*i+3] = f2tf32(br[i].w);
        }
    }
    __syncthreads();

    for (int t = 0; t < 16; t++) {
        int buf = t & 1;
        if (t < 15) {
            int kb = (t + 1) * 32;
#pragma unroll
            for (int i = 0; i < 4; i++) {
                ar[i] = *(const float4*)(A + (size_t)arow * lda + kb + acol + 4 * i);
                br[i] = *(const float4*)(W + (size_t)(kb + brow) * D_ + n0 + bcol + 4 * i);
            }
        }
        uint32_t* As = sm + buf * 4608;
        uint32_t* Bs = sm + 9216 + buf * 4224;
#pragma unroll
        for (int ks = 0; ks < 4; ks++) {
            int k0 = ks * 8;
            uint32_t af[4][4], bf[4][2];
#pragma unroll
            for (int mt = 0; mt < 4; mt++) {
                int r0 = wm + mt * 16 + group;
                af[mt][0] = As[r0 * SA_ + k0 + tig];
                af[mt][1] = As[(r0 + 8) * SA_ + k0 + tig];
                af[mt][2] = As[r0 * SA_ + k0 + tig + 4];
                af[mt][3] = As[(r0 + 8) * SA_ + k0 + tig + 4];
            }
#pragma unroll
            for (int nt = 0; nt < 4; nt++) {
                int c0 = wn + nt * 8 + group;
                bf[nt][0] = Bs[(k0 + tig) * SB_ + c0];
                bf[nt][1] = Bs[(k0 + tig + 4) * SB_ + c0];
            }
#pragma unroll
            for (int mt = 0; mt < 4; mt++)
#pragma unroll
                for (int nt = 0; nt < 4; nt++)
                    mma_tf32(acc[mt][nt], af[mt], bf[nt]);
        }
        if (t < 15) {
            int nb = buf ^ 1;
            uint32_t* da = sm + nb * 4608 + arow * SA_ + acol;
            uint32_t* db = sm + 9216 + nb * 4224 + brow * SB_ + bcol;
#pragma unroll
            for (int i = 0; i < 4; i++) {
                da[4*i+0] = f2tf32(ar[i].x); da[4*i+1] = f2tf32(ar[i].y);
                da[4*i+2] = f2tf32(ar[i].z); da[4*i+3] = f2tf32(ar[i].w);
                db[4*i+0] = f2tf32(br[i].x); db[4*i+1] = f2tf32(br[i].y);
                db[4*i+2] = f2tf32(br[i].z); db[4*i+3] = f2tf32(br[i].w);
            }
            __syncthreads();
        }
    }
}

// ---------------- K3: projections via mma.sync tf32 ----------------
__global__ __launch_bounds__(256) void proj_mma(
        const float* __restrict__ q, const float* __restrict__ k,
        const float* __restrict__ v,
        const float* __restrict__ wq, const float* __restrict__ wk,
        const float* __restrict__ wv,
        const float* __restrict__ bq, const float* __restrict__ bk,
        const float* __restrict__ bv) {
    extern __shared__ uint32_t smu[];
    int z = blockIdx.z;
    int b = z / 3, p = z % 3;
    int e = g_sel[b];
    const float* X = (p == 0 ? q : (p == 1 ? k : v)) + (size_t)b * S_ * D_;
    const float* W = (p == 0 ? wq : (p == 1 ? wk : wv)) + (size_t)e * D_ * D_;
    const float* bias = (p == 0 ? bq : (p == 1 ? bk : bv)) + e * D_;
    float* Out = (p == 0 ? g_qh : (p == 1 ? g_kh : g_vh));
    int bn = blockIdx.x * 128, m0 = blockIdx.y * 128;

    float acc[4][4][4] = {};
    mma_mainloop(smu, X + (size_t)m0 * D_, D_, W, bn, acc);

    const int lane = threadIdx.x & 31, wid = threadIdx.x >> 5;
    const int wm = (wid & 1) * 64, wn = (wid >> 1) * 32;
    const int group = lane >> 2, tig = lane & 3;

#pragma unroll
    for (int mt = 0; mt < 4; mt++) {
#pragma unroll
        for (int nt = 0; nt < 4; nt++) {
            int n = bn + wn + nt * 8 + 2 * tig;
            int m = m0 + wm + mt * 16 + group;
            int h = n >> 6, dk = n & 63;
            float b0v = bias[n], b1v = bias[n + 1];
            if (p < 2) {
                size_t base = ((size_t)(b * H_ + h) * DK_ + dk) * S_;
                Out[base + m]            = acc[mt][nt][0] + b0v;
                Out[base + S_ + m]       = acc[mt][nt][1] + b1v;
                Out[base + m + 8]        = acc[mt][nt][2] + b0v;
                Out[base + S_ + m + 8]   = acc[mt][nt][3] + b1v;
            } else {
                size_t base = ((size_t)(b * H_ + h) * S_ + m) * DK_ + dk;
                Out[base]                = acc[mt][nt][0] + b0v;
                Out[base + 1]            = acc[mt][nt][1] + b1v;
                Out[base + 8 * DK_]      = acc[mt][nt][2] + b0v;
                Out[base + 8 * DK_ + 1]  = acc[mt][nt][3] + b1v;
            }
        }
    }
}

// ---------------- K5: final projection via mma.sync tf32 ----------------
__global__ __launch_bounds__(256) void final_mma(const float* __restrict__ wo,
                                                 const float* __restrict__ bo,
                                                 float* __restrict__ out) {
    extern __shared__ uint32_t smu[];
    int b = blockIdx.z;
    int e = g_sel[b];
    const float* A = g_ctx + (size_t)b * S_ * D_;
    const float* W = wo + (size_t)e * D_ * D_;
    const float* bias = bo + e * D_;
    int bn = blockIdx.x * 128, m0 = blockIdx.y * 128;

    float acc[4][4][4] = {};
    mma_mainloop(smu, A + (size_t)m0 * D_, D_, W, bn, acc);

    const int lane = threadIdx.x & 31, wid = threadIdx.x >> 5;
    const int wm = (wid & 1) * 64, wn = (wid >> 1) * 32;
    const int group = lane >> 2, tig = lane & 3;

#pragma unroll
    for (int mt = 0; mt < 4; mt++) {
#pragma unroll
        for (int nt = 0; nt < 4; nt++) {
            int n = bn + wn + nt * 8 + 2 * tig;
            int m = m0 + wm + mt * 16 + group;
            float b0v = bias[n], b1v = bias[n + 1];
            float* d0 = out + ((size_t)b * S_ + m) * D_ + n;
            d0[0]            = acc[mt][nt][0] + b0v;
            d0[1]            = acc[mt][nt][1] + b1v;
            d0[8 * D_]       = acc[mt][nt][2] + b0v;
            d0[8 * D_ + 1]   = acc[mt][nt][3] + b1v;
        }
    }
}

// ---------------- K4: fused attention (unchanged, fp32) ----------------
__global__ __launch_bounds__(256) void fused_attn_kernel(const int* __restrict__ mask) {
    extern __shared__ float smf[];
    float* Kt = smf;
    float* Vs = smf + 16384;
    float* Ps = smf + 32768;
    float* Qt = smf + 49152;

    int z = blockIdx.x;
    int b = z >> 3, h = z & 7;
    int tid = threadIdx.x;

    const float4* ksrc = (const float4*)(g_kh + (size_t)z * 16384);
    const float4* vsrc = (const float4*)(g_vh + (size_t)z * 16384);
    float4* kdst = (float4*)Kt;
    float4* vdst = (float4*)Vs;
#pragma unroll
    for (int i = 0; i < 16; i++) {
        kdst[tid + i * 256] = ksrc[tid + i * 256];
        vdst[tid + i * 256] = vsrc[tid + i * 256];
    }

    int ty = tid >> 5, txx = tid & 31;
    int ty2 = tid >> 4, tx2 = tid & 15;

    for (int qt = 0; qt < 4; qt++) {
        const float* qsrc = g_qh + (size_t)z * 16384 + qt * 64;
#pragma unroll
        for (int i = 0; i < 4; i++) {
            int lin = tid + i * 256;
            int dk = lin >> 4, c = (lin & 15) * 4;
            *(float4*)&Qt[dk * 64 + c] = *(const float4*)(qsrc + (size_t)dk * S_ + c);
        }
        __syncthreads();

        float p[8][8] = {};
#pragma unroll 4
        for (int dk = 0; dk < 64; dk++) {
            float4 x0 = *(const float4*)&Qt[dk * 64 + ty * 8];
            float4 x1 = *(const float4*)&Qt[dk * 64 + ty * 8 + 4];
            float4 y0 = *(const float4*)&Kt[dk * 256 + txx * 8];
            float4 y1 = *(const float4*)&Kt[dk * 256 + txx * 8 + 4];
            float a[8] = {x0.x, x0.y, x0.z, x0.w, x1.x, x1.y, x1.z, x1.w};
            float bb[8] = {y0.x, y0.y, y0.z, y0.w, y1.x, y1.y, y1.z, y1.w};
#pragma unroll
            for (int i = 0; i < 8; i++)
#pragma unroll
                for (int j = 0; j < 8; j++) p[i][j] = fmaf(a[i], bb[j], p[i][j]);
        }

#pragma unroll
        for (int i = 0; i < 8; i++) {
            int r = qt * 64 + ty * 8 + i;
            int4 m0 = *(const int4*)&mask[r * S_ + txx * 8];
            int4 m1 = *(const int4*)&mask[r * S_ + txx * 8 + 4];
            p[i][0] = (m0.x == 0) ? -1e9f : p[i][0] * 0.125f;
            p[i][1] = (m0.y == 0) ? -1e9f : p[i][1] * 0.125f;
            p[i][2] = (m0.z == 0) ? -1e9f : p[i][2] * 0.125f;
            p[i][3] = (m0.w == 0) ? -1e9f : p[i][3] * 0.125f;
            p[i][4] = (m1.x == 0) ? -1e9f : p[i][4] * 0.125f;
            p[i][5] = (m1.y == 0) ? -1e9f : p[i][5] * 0.125f;
            p[i][6] = (m1.z == 0) ? -1e9f : p[i][6] * 0.125f;
            p[i][7] = (m1.w == 0) ? -1e9f : p[i][7] * 0.125f;

            float mx = p[i][0];
#pragma unroll
            for (int j = 1; j < 8; j++) mx = fmaxf(mx, p[i][j]);
#pragma unroll
            for (int off = 16; off > 0; off >>= 1)
                mx = fmaxf(mx, __shfl_xor_sync(0xffffffffu, mx, off));
            float sum = 0.0f;
#pragma unroll
            for (int j = 0; j < 8; j++) { p[i][j] = expf(p[i][j] - mx); sum += p[i][j]; }
#pragma unroll
            for (int off = 16; off > 0; off >>= 1)
                sum += __shfl_xor_sync(0xffffffffu, sum, off);
            float inv = 1.0f / sum;
#pragma unroll
            for (int j = 0; j < 8; j++) p[i][j] *= inv;
        }

#pragma unroll
        for (int i = 0; i < 8; i++) {
            *(float4*)&Ps[(ty * 8 + i) * 256 + txx * 8] =
                make_float4(p[i][0], p[i][1], p[i][2], p[i][3]);
            *(float4*)&Ps[(ty * 8 + i) * 256 + txx * 8 + 4] =
                make_float4(p[i][4], p[i][5], p[i][6], p[i][7]);
        }
        __syncthreads();

        float c2[4][4] = {};
#pragma unroll 2
        for (int kc = 0; kc < 256; kc += 4) {
            float4 av[4], bv[4];
#pragma unroll
            for (int i = 0; i < 4; i++) av[i] = *(const float4*)&Ps[(ty2 * 4 + i) * 256 + kc];
#pragma unroll
            for (int t = 0; t < 4; t++) bv[t] = *(const float4*)&Vs[(kc + t) * 64 + tx2 * 4];
            float aa[4][4] = {{av[0].x, av[0].y, av[0].z, av[0].w},
                              {av[1].x, av[1].y, av[1].z, av[1].w},
                              {av[2].x, av[2].y, av[2].z, av[2].w},
                              {av[3].x, av[3].y, av[3].z, av[3].w}};
            float bb2[4][4] = {{bv[0].x, bv[0].y, bv[0].z, bv[0].w},
                               {bv[1].x, bv[1].y, bv[1].z, bv[1].w},
                               {bv[2].x, bv[2].y, bv[2].z, bv[2].w},
                               {bv[3].x, bv[3].y, bv[3].z, bv[3].w}};
#pragma unroll
            for (int t = 0; t < 4; t++)
#pragma unroll
                for (int i = 0; i < 4; i++)
#pragma unroll
                    for (int j = 0; j < 4; j++)
                        c2[i][j] = fmaf(aa[i][t], bb2[t][j], c2[i][j]);
        }

#pragma unroll
        for (int i = 0; i < 4; i++) {
            int s = qt * 64 + ty2 * 4 + i;
            *(float4*)&g_ctx[((size_t)b * S_ + s) * D_ + h * DK_ + tx2 * 4] =
                make_float4(c2[i][0], c2[i][1], c2[i][2], c2[i][3]);
        }
    }
}

// ---------------- launch ----------------
extern "C" void kernel_launch(void* const* d_in, const int* in_sizes, int n_in,
                              void* d_out, int out_size) {
    const float* q    = (const float*)d_in[0];
    const float* k    = (const float*)d_in[1];
    const float* v    = (const float*)d_in[2];
    const int*   mask = (const int*)  d_in[3];
    const float* wg   = (const float*)d_in[4];
    const float* wn   = (const float*)d_in[5];
    const float* wq   = (const float*)d_in[6];
    const float* bq   = (const float*)d_in[7];
    const float* wk   = (const float*)d_in[8];
    const float* bk   = (const float*)d_in[9];
    const float* wv   = (const float*)d_in[10];
    const float* bv   = (const float*)d_in[11];
    const float* wo   = (const float*)d_in[12];
    const float* bo   = (const float*)d_in[13];
    float* out = (float*)d_out;

    const int attn_smem = (16384 * 3 + 4096) * 4;
    cudaFuncSetAttribute(fused_attn_kernel,
                         cudaFuncAttributeMaxDynamicSharedMemorySize, attn_smem);
    cudaFuncSetAttribute(proj_mma,
                         cudaFuncAttributeMaxDynamicSharedMemorySize, MMA_SMEM_BYTES);
    cudaFuncSetAttribute(final_mma,
                         cudaFuncAttributeMaxDynamicSharedMemorySize, MMA_SMEM_BYTES);

    xsum_kernel<<<B_, 512>>>(q);
    gating_kernel<<<1, 128>>>(wg, wn, out, out_size);
    proj_mma<<<dim3(4, 2, B_ * 3), 256, MMA_SMEM_BYTES>>>(q, k, v, wq, wk, wv, bq, bk, bv);
    fused_attn_kernel<<<B_ * H_, 256, attn_smem>>>(mask);
    final_mma<<<dim3(4, 2, B_), 256, MMA_SMEM_BYTES>>>(wo, bo, out);
}